// round 6
// baseline (speedup 1.0000x reference)
#include <cuda_runtime.h>
#include <cuda_fp16.h>
#include <cstdint>

#define NN   8192
#define FIN  256
#define FOUT 128
#define NC   128        // j-chunks of 64
#define BM   64         // rows per CTA in main kernel
#define GRID_MAIN (NN / BM)   // 128

// ---------------- scratch (static device globals; no allocation) ----------------
__device__ __align__(16) __half g_Wh16[(size_t)NN * FOUT];  // [row j][col c] fp16
__device__ __align__(16) float g_nf1[NN];   // -f1
__device__ __align__(16) float g_H1 [NN];   // exp(-0.8 f1)
__device__ __align__(16) float g_f2 [NN];
__device__ __align__(16) float g_E2 [NN];   // exp(f2)
__device__ __align__(16) float g_G2 [NN];   // exp(0.2 f2)

__device__ __forceinline__ uint32_t sptr(const void* p) {
    return (uint32_t)__cvta_generic_to_shared(p);
}

// =====================================================================
// Kernel 1: Wh = h @ W (fp32 SIMT GEMM) fused with fp16 output and the
// f1/f2 row reductions + exp vectors. grid 256, block 256. BM=32.
// =====================================================================
__global__ __launch_bounds__(256) void wh_gemm_kernel(
    const float* __restrict__ h, const float* __restrict__ Wm,
    const float* __restrict__ a)
{
    __shared__ float hs[32][33];
    __shared__ float Ws[32][132];
    const int tid = threadIdx.x;
    const int i0  = blockIdx.x * 32;
    const int ty  = tid >> 4, tx = tid & 15;

    float acc[2][8];
#pragma unroll
    for (int u = 0; u < 2; u++)
#pragma unroll
        for (int v = 0; v < 8; v++) acc[u][v] = 0.0f;

    for (int k0 = 0; k0 < FIN; k0 += 32) {
        __syncthreads();
        {   int r = tid >> 3, c = (tid & 7) * 4;
            float4 v = *(const float4*)&h[(size_t)(i0 + r) * FIN + k0 + c];
            hs[r][c+0]=v.x; hs[r][c+1]=v.y; hs[r][c+2]=v.z; hs[r][c+3]=v.w;
        }
        {   int r = tid >> 3, c = (tid & 7) * 16;
#pragma unroll
            for (int q = 0; q < 4; q++) {
                float4 v = *(const float4*)&Wm[(size_t)(k0 + r) * FOUT + c + 4*q];
                Ws[r][c+4*q+0]=v.x; Ws[r][c+4*q+1]=v.y; Ws[r][c+4*q+2]=v.z; Ws[r][c+4*q+3]=v.w;
            }
        }
        __syncthreads();
#pragma unroll 8
        for (int k = 0; k < 32; k++) {
            float a0 = hs[2*ty][k], a1 = hs[2*ty+1][k];
            float4 b0 = *(const float4*)&Ws[k][8*tx];
            float4 b1 = *(const float4*)&Ws[k][8*tx + 4];
            float bv[8] = {b0.x,b0.y,b0.z,b0.w,b1.x,b1.y,b1.z,b1.w};
#pragma unroll
            for (int v = 0; v < 8; v++) {
                acc[0][v] = fmaf(a0, bv[v], acc[0][v]);
                acc[1][v] = fmaf(a1, bv[v], acc[1][v]);
            }
        }
    }

    float f1a[2] = {0.f, 0.f}, f2a[2] = {0.f, 0.f};
#pragma unroll
    for (int u = 0; u < 2; u++) {
        int row = i0 + 2*ty + u;
#pragma unroll
        for (int q = 0; q < 4; q++) {
            *(__half2*)&g_Wh16[(size_t)row * FOUT + 8*tx + 2*q] =
                __floats2half2_rn(acc[u][2*q], acc[u][2*q+1]);
        }
#pragma unroll
        for (int v = 0; v < 8; v++) {
            int col = 8*tx + v;
            f1a[u] = fmaf(acc[u][v], a[col],        f1a[u]);
            f2a[u] = fmaf(acc[u][v], a[FOUT + col], f2a[u]);
        }
    }
#pragma unroll
    for (int o = 8; o > 0; o >>= 1) {
        f1a[0] += __shfl_xor_sync(0xffffffffu, f1a[0], o);
        f1a[1] += __shfl_xor_sync(0xffffffffu, f1a[1], o);
        f2a[0] += __shfl_xor_sync(0xffffffffu, f2a[0], o);
        f2a[1] += __shfl_xor_sync(0xffffffffu, f2a[1], o);
    }
    if (tx == 0) {
#pragma unroll
        for (int u = 0; u < 2; u++) {
            int i = i0 + 2*ty + u;
            float f1 = f1a[u], f2 = f2a[u];
            g_nf1[i] = -f1;
            g_H1[i]  = expf(-0.8f * f1);
            g_f2[i]  = f2;
            g_E2[i]  = expf(f2);
            g_G2[i]  = expf(0.2f * f2);
        }
    }
}

// =====================================================================
// Kernel 2: fused masked-softmax-attention, fp16 mma.sync.
// 512 threads (16 warps, 4m x 4n, warp tile m16n32), BM=64, grid 128.
// NO cp.async anywhere (LDGSTS rt=8cyc/op was the R5 bottleneck):
//   adj: LDG.128 -> register ring depth 4, consumed directly by pgen
//   B:   LDG.128 -> regs (1 iter) -> STS, double-buffered sB
// sP double-buffered; exactly one __syncthreads per chunk.
// =====================================================================
__device__ __forceinline__ void mma_fp16(float* c, const uint32_t* a,
                                         uint32_t b0, uint32_t b1)
{
    asm volatile(
        "mma.sync.aligned.m16n8k16.row.col.f32.f16.f16.f32 "
        "{%0,%1,%2,%3},{%4,%5,%6,%7},{%8,%9},{%0,%1,%2,%3};\n"
        : "+f"(c[0]), "+f"(c[1]), "+f"(c[2]), "+f"(c[3])
        : "r"(a[0]), "r"(a[1]), "r"(a[2]), "r"(a[3]), "r"(b0), "r"(b1));
}

#define SP_SLOT  9216u       // 64 x 72 halfs
#define SB_SLOT  17408u      // 64 x 136 halfs
#define DYN_SMEM (2*SP_SLOT + 2*SB_SLOT)   // 53248

__global__ __launch_bounds__(512, 1) void gat_main_kernel(
    const int* __restrict__ adj, float* __restrict__ out)
{
    extern __shared__ char dynsm[];
    __shared__ float sden[BM];

    const int tid  = threadIdx.x;
    const int lane = tid & 31;
    const int warp = tid >> 5;
    const int r    = tid >> 3;     // 0..63  (pgen/adj row)
    const int cb   = tid & 7;      // col block of 8
    const int i0   = blockIdx.x * BM;
    const int wm   = warp & 3;     // m16 position
    const int wn   = warp >> 2;    // n32 position

    const uint32_t spS = sptr(dynsm);
    const uint32_t sbS = spS + 2 * SP_SLOT;

    const float nf1r = g_nf1[i0 + r];
    const float H1r  = g_H1 [i0 + r];
    float den = 0.0f;

    float acc[4][4];
#pragma unroll
    for (int nf = 0; nf < 4; nf++)
#pragma unroll
        for (int q = 0; q < 4; q++) acc[nf][q] = 0.0f;

    // per-thread source pointers
    const int*    adjrow = &adj[(size_t)(i0 + r) * NN + 8 * cb];
    const __half* bsrc0  = &g_Wh16[(size_t)(tid >> 4)        * FOUT + 8 * (tid & 15)];
    const __half* bsrc1  = &g_Wh16[(size_t)((tid >> 4) + 32) * FOUT + 8 * (tid & 15)];
    const uint32_t bdst0 = sbS + (uint32_t)(tid >> 4) * 272u + 16u * (tid & 15);
    const uint32_t bdst1 = bdst0 + 32u * 272u;

    int4 areg[4][2];    // adj register ring, depth 4
    int4 breg[2][2];    // B regs held one iteration

    auto ldAdj = [&](int ch) {
        if (ch < NC) {
            areg[ch & 3][0] = *(const int4*)&adjrow[ch * 64];
            areg[ch & 3][1] = *(const int4*)&adjrow[ch * 64 + 4];
        }
    };
    auto ldB = [&](int ch, int4* br) {
        if (ch < NC) {
            const size_t off = (size_t)(ch * 64) * FOUT;
            br[0] = *(const int4*)(bsrc0 + off);
            br[1] = *(const int4*)(bsrc1 + off);
        }
    };
    auto stB = [&](int ch, const int4* br) {
        if (ch < NC) {
            uint32_t base = (uint32_t)(ch & 1) * SB_SLOT;
            asm volatile("st.shared.v4.b32 [%0],{%1,%2,%3,%4};"
                         :: "r"(bdst0 + base), "r"(br[0].x), "r"(br[0].y),
                            "r"(br[0].z), "r"(br[0].w) : "memory");
            asm volatile("st.shared.v4.b32 [%0],{%1,%2,%3,%4};"
                         :: "r"(bdst1 + base), "r"(br[1].x), "r"(br[1].y),
                            "r"(br[1].z), "r"(br[1].w) : "memory");
        }
    };

    auto pgen = [&](int ch) {
        const int j0 = ch * 64, c0 = 8 * cb;
        int4 a0 = areg[ch & 3][0], a1 = areg[ch & 3][1];
        float4 f2v0 = __ldg((const float4*)&g_f2[j0 + c0]);
        float4 f2v1 = __ldg((const float4*)&g_f2[j0 + c0 + 4]);
        float4 E2v0 = __ldg((const float4*)&g_E2[j0 + c0]);
        float4 E2v1 = __ldg((const float4*)&g_E2[j0 + c0 + 4]);
        float4 G2v0 = __ldg((const float4*)&g_G2[j0 + c0]);
        float4 G2v1 = __ldg((const float4*)&g_G2[j0 + c0 + 4]);
        float w[8];
        w[0] = (a0.x > 0) ? ((f2v0.x > nf1r) ? E2v0.x : H1r * G2v0.x) : 0.0f;
        w[1] = (a0.y > 0) ? ((f2v0.y > nf1r) ? E2v0.y : H1r * G2v0.y) : 0.0f;
        w[2] = (a0.z > 0) ? ((f2v0.z > nf1r) ? E2v0.z : H1r * G2v0.z) : 0.0f;
        w[3] = (a0.w > 0) ? ((f2v0.w > nf1r) ? E2v0.w : H1r * G2v0.w) : 0.0f;
        w[4] = (a1.x > 0) ? ((f2v1.x > nf1r) ? E2v1.x : H1r * G2v1.x) : 0.0f;
        w[5] = (a1.y > 0) ? ((f2v1.y > nf1r) ? E2v1.y : H1r * G2v1.y) : 0.0f;
        w[6] = (a1.z > 0) ? ((f2v1.z > nf1r) ? E2v1.z : H1r * G2v1.z) : 0.0f;
        w[7] = (a1.w > 0) ? ((f2v1.w > nf1r) ? E2v1.w : H1r * G2v1.w) : 0.0f;
        uint32_t u[4];
#pragma unroll
        for (int q = 0; q < 4; q++) {
            __half2 pk = __floats2half2_rn(fminf(w[2*q], 60000.f),
                                           fminf(w[2*q+1], 60000.f));
            u[q] = *(uint32_t*)&pk;
            // denominator from the SAME fp16-rounded weights the MMA sees
            den += __low2float(pk) + __high2float(pk);
        }
        uint32_t dst = spS + (uint32_t)(ch & 1) * SP_SLOT
                     + (uint32_t)(r * 144 + c0 * 2);
        asm volatile("st.shared.v4.b32 [%0],{%1,%2,%3,%4};"
                     :: "r"(dst), "r"(u[0]), "r"(u[1]), "r"(u[2]), "r"(u[3]) : "memory");
    };

    auto mma_phase = [&](int ch) {
        uint32_t sp = spS + (uint32_t)(ch & 1) * SP_SLOT;
        uint32_t sb = sbS + (uint32_t)(ch & 1) * SB_SLOT;
        const int mi = lane >> 3, l7 = lane & 7;
#pragma unroll
        for (int kk = 0; kk < 4; kk++) {
            uint32_t afr[4];
            {
                uint32_t addr = sp + (uint32_t)((16*wm + ((mi & 1) << 3) + l7) * 144
                                                + (16*kk + ((mi >> 1) << 3)) * 2);
                asm volatile(
                    "ldmatrix.sync.aligned.m8n8.x4.shared.b16 {%0,%1,%2,%3},[%4];\n"
                    : "=r"(afr[0]), "=r"(afr[1]), "=r"(afr[2]), "=r"(afr[3])
                    : "r"(addr));
            }
#pragma unroll
            for (int nfp = 0; nfp < 2; nfp++) {
                int n0 = 32*wn + 16*nfp;
                uint32_t b[4];
                uint32_t addr = sb + (uint32_t)((16*kk + ((mi & 1) << 3) + l7) * 272
                                                + (n0 + ((mi >> 1) << 3)) * 2);
                asm volatile(
                    "ldmatrix.sync.aligned.m8n8.x4.trans.shared.b16 {%0,%1,%2,%3},[%4];\n"
                    : "=r"(b[0]), "=r"(b[1]), "=r"(b[2]), "=r"(b[3])
                    : "r"(addr));
                mma_fp16(acc[2*nfp],     afr, b[0], b[1]);
                mma_fp16(acc[2*nfp + 1], afr, b[2], b[3]);
            }
        }
    };

    // ---- prologue ----
    ldAdj(0); ldAdj(1); ldAdj(2);
    {
        int4 b0t[2];
        ldB(0, b0t);
        stB(0, b0t);          // stalls on LDG once; fine
        ldB(1, breg[1]);      // consumed (STS'd) at iter 0
    }

    // ---- main loop: 1 barrier per chunk ----
    for (int ch = 0; ch < NC; ch++) {
        ldAdj(ch + 3);
        ldB(ch + 2, breg[ch & 1]);
        pgen(ch);
        __syncthreads();
        stB(ch + 1, breg[(ch + 1) & 1]);
        mma_phase(ch);
    }

    // ---- denominator reduction (8 threads per row) ----
    den += __shfl_xor_sync(0xffffffffu, den, 1);
    den += __shfl_xor_sync(0xffffffffu, den, 2);
    den += __shfl_xor_sync(0xffffffffu, den, 4);
    if (cb == 0) sden[r] = den;
    __syncthreads();

    // ---- epilogue: normalize, write fp32 output ----
    const int g = lane >> 2, t = lane & 3;
    {
        int row0 = 16*wm + g;
        float inv0 = 1.0f / sden[row0];
        float inv1 = 1.0f / sden[row0 + 8];
#pragma unroll
        for (int nf = 0; nf < 4; nf++) {
            int col = 32*wn + 8*nf + 2*t;
            out[(size_t)(i0 + row0)     * FOUT + col    ] = acc[nf][0] * inv0;
            out[(size_t)(i0 + row0)     * FOUT + col + 1] = acc[nf][1] * inv0;
            out[(size_t)(i0 + row0 + 8) * FOUT + col    ] = acc[nf][2] * inv1;
            out[(size_t)(i0 + row0 + 8) * FOUT + col + 1] = acc[nf][3] * inv1;
        }
    }
}

// =====================================================================
extern "C" void kernel_launch(void* const* d_in, const int* in_sizes, int n_in,
                              void* d_out, int out_size)
{
    const float* h   = (const float*)d_in[0];   // [8192,256] f32
    const int*   adj = (const int*)  d_in[1];   // [8192,8192] i32
    const float* Wm  = (const float*)d_in[2];   // [256,128] f32
    const float* a   = (const float*)d_in[3];   // [256,1] f32
    float* out = (float*)d_out;                 // [8192,128] f32

    cudaFuncSetAttribute(gat_main_kernel,
                         cudaFuncAttributeMaxDynamicSharedMemorySize, DYN_SMEM);

    wh_gemm_kernel <<<256, 256>>>(h, Wm, a);
    gat_main_kernel<<<GRID_MAIN, 512, DYN_SMEM>>>(adj, out);
}

// round 7
// speedup vs baseline: 1.4321x; 1.4321x over previous
#include <cuda_runtime.h>
#include <cuda_fp16.h>
#include <cstdint>

#define NN   8192
#define FIN  256
#define FOUT 128
#define NC   128        // j-chunks of 64
#define BM   32         // rows per CTA in main kernel
#define GRID_MAIN (NN / BM)   // 256

// ---------------- scratch (static device globals; no allocation) ----------------
__device__ __align__(16) __half g_Wh16[(size_t)NN * FOUT];  // [row j][col c] fp16
__device__ __align__(16) float g_nf1[NN];   // -f1
__device__ __align__(16) float g_H1 [NN];   // exp(-0.8 f1)
__device__ __align__(16) float g_f2 [NN];
__device__ __align__(16) float g_E2 [NN];   // exp(f2)
__device__ __align__(16) float g_G2 [NN];   // exp(0.2 f2)

__device__ __forceinline__ uint32_t sptr(const void* p) {
    return (uint32_t)__cvta_generic_to_shared(p);
}

// =====================================================================
// Kernel 1: Wh = h @ W (fp32 SIMT GEMM) fused with fp16 output and the
// f1/f2 row reductions + exp vectors. grid 256, block 256, 2 CTAs/SM.
// =====================================================================
__global__ __launch_bounds__(256, 2) void wh_gemm_kernel(
    const float* __restrict__ h, const float* __restrict__ Wm,
    const float* __restrict__ a)
{
    __shared__ float hs[32][33];
    __shared__ float Ws[32][132];
    const int tid = threadIdx.x;
    const int i0  = blockIdx.x * 32;
    const int ty  = tid >> 4, tx = tid & 15;

    float acc[2][8];
#pragma unroll
    for (int u = 0; u < 2; u++)
#pragma unroll
        for (int v = 0; v < 8; v++) acc[u][v] = 0.0f;

    for (int k0 = 0; k0 < FIN; k0 += 32) {
        __syncthreads();
        {   int r = tid >> 3, c = (tid & 7) * 4;
            float4 v = *(const float4*)&h[(size_t)(i0 + r) * FIN + k0 + c];
            hs[r][c+0]=v.x; hs[r][c+1]=v.y; hs[r][c+2]=v.z; hs[r][c+3]=v.w;
        }
        {   int r = tid >> 3, c = (tid & 7) * 16;
#pragma unroll
            for (int q = 0; q < 4; q++) {
                float4 v = *(const float4*)&Wm[(size_t)(k0 + r) * FOUT + c + 4*q];
                Ws[r][c+4*q+0]=v.x; Ws[r][c+4*q+1]=v.y; Ws[r][c+4*q+2]=v.z; Ws[r][c+4*q+3]=v.w;
            }
        }
        __syncthreads();
#pragma unroll 8
        for (int k = 0; k < 32; k++) {
            float a0 = hs[2*ty][k], a1 = hs[2*ty+1][k];
            float4 b0 = *(const float4*)&Ws[k][8*tx];
            float4 b1 = *(const float4*)&Ws[k][8*tx + 4];
            float bv[8] = {b0.x,b0.y,b0.z,b0.w,b1.x,b1.y,b1.z,b1.w};
#pragma unroll
            for (int v = 0; v < 8; v++) {
                acc[0][v] = fmaf(a0, bv[v], acc[0][v]);
                acc[1][v] = fmaf(a1, bv[v], acc[1][v]);
            }
        }
    }

    float f1a[2] = {0.f, 0.f}, f2a[2] = {0.f, 0.f};
#pragma unroll
    for (int u = 0; u < 2; u++) {
        int row = i0 + 2*ty + u;
#pragma unroll
        for (int q = 0; q < 4; q++) {
            *(__half2*)&g_Wh16[(size_t)row * FOUT + 8*tx + 2*q] =
                __floats2half2_rn(acc[u][2*q], acc[u][2*q+1]);
        }
#pragma unroll
        for (int v = 0; v < 8; v++) {
            int col = 8*tx + v;
            f1a[u] = fmaf(acc[u][v], a[col],        f1a[u]);
            f2a[u] = fmaf(acc[u][v], a[FOUT + col], f2a[u]);
        }
    }
#pragma unroll
    for (int o = 8; o > 0; o >>= 1) {
        f1a[0] += __shfl_xor_sync(0xffffffffu, f1a[0], o);
        f1a[1] += __shfl_xor_sync(0xffffffffu, f1a[1], o);
        f2a[0] += __shfl_xor_sync(0xffffffffu, f2a[0], o);
        f2a[1] += __shfl_xor_sync(0xffffffffu, f2a[1], o);
    }
    if (tx == 0) {
#pragma unroll
        for (int u = 0; u < 2; u++) {
            int i = i0 + 2*ty + u;
            float f1 = f1a[u], f2 = f2a[u];
            g_nf1[i] = -f1;
            g_H1[i]  = expf(-0.8f * f1);
            g_f2[i]  = f2;
            g_E2[i]  = expf(f2);
            g_G2[i]  = expf(0.2f * f2);
        }
    }
}

// =====================================================================
// Kernel 2: fused masked-softmax-attention, fp16 mma.sync.
// 256 threads (8 warps, 2m x 4n, warp tile m16n32), BM=32, grid 256
// -> 2 CTAs/SM co-resident (the R5 kernel was 1 CTA/SM latency-bound).
// adj via cp.async 4-deep SMEM ring (self-consumed), sP/sB triple-buffered,
// counted cp.async groups (race-free accounting), 1 barrier per chunk.
// =====================================================================
__device__ __forceinline__ void mma_fp16(float* c, const uint32_t* a,
                                         uint32_t b0, uint32_t b1)
{
    asm volatile(
        "mma.sync.aligned.m16n8k16.row.col.f32.f16.f16.f32 "
        "{%0,%1,%2,%3},{%4,%5,%6,%7},{%8,%9},{%0,%1,%2,%3};\n"
        : "+f"(c[0]), "+f"(c[1]), "+f"(c[2]), "+f"(c[3])
        : "r"(a[0]), "r"(a[1]), "r"(a[2]), "r"(a[3]), "r"(b0), "r"(b1));
}

#define ADJ_SLOT 8192u       // 32 x 64 ints
#define SP_SLOT  4608u       // 32 x 72 halfs
#define SB_SLOT  17408u      // 64 x 136 halfs
#define DYN_SMEM (4*ADJ_SLOT + 3*SP_SLOT + 3*SB_SLOT)   // 98816

__global__ __launch_bounds__(256, 2) void gat_main_kernel(
    const int* __restrict__ adj, float* __restrict__ out)
{
    extern __shared__ char dynsm[];
    __shared__ float sden[BM];

    const int tid  = threadIdx.x;
    const int lane = tid & 31;
    const int warp = tid >> 5;
    const int r    = tid >> 3;     // 0..31  (pgen/adj row)
    const int cb   = tid & 7;      // col block of 8
    const int i0   = blockIdx.x * BM;
    const int wm   = warp & 1;     // m16 position (2)
    const int wn   = warp >> 1;    // n32 position (4)

    const uint32_t adjS = sptr(dynsm);
    const uint32_t spS  = adjS + 4 * ADJ_SLOT;
    const uint32_t sbS  = spS  + 3 * SP_SLOT;

    const float nf1r = g_nf1[i0 + r];
    const float H1r  = g_H1 [i0 + r];
    float den = 0.0f;

    float acc[4][4];
#pragma unroll
    for (int nf = 0; nf < 4; nf++)
#pragma unroll
        for (int q = 0; q < 4; q++) acc[nf][q] = 0.0f;

    // ---- stage helpers (each always commits exactly one group) ----
    auto stage_adj = [&](int ch) {
        if (ch < NC) {
            const int* src = &adj[(size_t)(i0 + r) * NN + ch * 64 + 8 * cb];
            uint32_t dst = adjS + (uint32_t)(ch & 3) * ADJ_SLOT
                         + (uint32_t)(r * 256 + 32 * cb);
            asm volatile("cp.async.cg.shared.global [%0],[%1],16;\n" :: "r"(dst), "l"(src));
            asm volatile("cp.async.cg.shared.global [%0],[%1],16;\n" :: "r"(dst+16u), "l"(src+4));
        }
        asm volatile("cp.async.commit_group;\n");
    };
    auto stage_B = [&](int ch) {
        if (ch < NC) {
            const int j0 = ch * 64;
            uint32_t base = sbS + (uint32_t)(ch % 3) * SB_SLOT;
#pragma unroll
            for (int i = 0; i < 4; i++) {
                int seg = tid + 256 * i;          // 0..1023
                int rr = seg >> 4, ss = seg & 15;
                const __half* src = &g_Wh16[(size_t)(j0 + rr) * FOUT + 8 * ss];
                uint32_t dst = base + (uint32_t)(rr * 272 + 16 * ss);
                asm volatile("cp.async.cg.shared.global [%0],[%1],16;\n" :: "r"(dst), "l"(src));
            }
        }
        asm volatile("cp.async.commit_group;\n");
    };

    auto pgen = [&](int ch) {
        const int j0 = ch * 64, c0 = 8 * cb;
        uint32_t aoff = adjS + (uint32_t)(ch & 3) * ADJ_SLOT
                      + (uint32_t)(r * 256 + 32 * cb);
        int4 a0, a1;
        asm volatile("ld.shared.v4.b32 {%0,%1,%2,%3},[%4];"
                     : "=r"(a0.x), "=r"(a0.y), "=r"(a0.z), "=r"(a0.w) : "r"(aoff));
        asm volatile("ld.shared.v4.b32 {%0,%1,%2,%3},[%4];"
                     : "=r"(a1.x), "=r"(a1.y), "=r"(a1.z), "=r"(a1.w) : "r"(aoff + 16u));
        float4 f2v0 = __ldg((const float4*)&g_f2[j0 + c0]);
        float4 f2v1 = __ldg((const float4*)&g_f2[j0 + c0 + 4]);
        float4 E2v0 = __ldg((const float4*)&g_E2[j0 + c0]);
        float4 E2v1 = __ldg((const float4*)&g_E2[j0 + c0 + 4]);
        float4 G2v0 = __ldg((const float4*)&g_G2[j0 + c0]);
        float4 G2v1 = __ldg((const float4*)&g_G2[j0 + c0 + 4]);
        float w[8];
        w[0] = (a0.x > 0) ? ((f2v0.x > nf1r) ? E2v0.x : H1r * G2v0.x) : 0.0f;
        w[1] = (a0.y > 0) ? ((f2v0.y > nf1r) ? E2v0.y : H1r * G2v0.y) : 0.0f;
        w[2] = (a0.z > 0) ? ((f2v0.z > nf1r) ? E2v0.z : H1r * G2v0.z) : 0.0f;
        w[3] = (a0.w > 0) ? ((f2v0.w > nf1r) ? E2v0.w : H1r * G2v0.w) : 0.0f;
        w[4] = (a1.x > 0) ? ((f2v1.x > nf1r) ? E2v1.x : H1r * G2v1.x) : 0.0f;
        w[5] = (a1.y > 0) ? ((f2v1.y > nf1r) ? E2v1.y : H1r * G2v1.y) : 0.0f;
        w[6] = (a1.z > 0) ? ((f2v1.z > nf1r) ? E2v1.z : H1r * G2v1.z) : 0.0f;
        w[7] = (a1.w > 0) ? ((f2v1.w > nf1r) ? E2v1.w : H1r * G2v1.w) : 0.0f;
        uint32_t u[4];
#pragma unroll
        for (int q = 0; q < 4; q++) {
            __half2 pk = __floats2half2_rn(fminf(w[2*q], 60000.f),
                                           fminf(w[2*q+1], 60000.f));
            u[q] = *(uint32_t*)&pk;
            // denominator from the SAME fp16-rounded weights the MMA sees
            den += __low2float(pk) + __high2float(pk);
        }
        uint32_t dst = spS + (uint32_t)(ch % 3) * SP_SLOT
                     + (uint32_t)(r * 144 + c0 * 2);
        asm volatile("st.shared.v4.b32 [%0],{%1,%2,%3,%4};"
                     :: "r"(dst), "r"(u[0]), "r"(u[1]), "r"(u[2]), "r"(u[3]) : "memory");
    };

    auto mma_phase = [&](int ch) {
        uint32_t sp = spS + (uint32_t)(ch % 3) * SP_SLOT;
        uint32_t sb = sbS + (uint32_t)(ch % 3) * SB_SLOT;
        const int mi = lane >> 3, l7 = lane & 7;
#pragma unroll
        for (int kk = 0; kk < 4; kk++) {
            uint32_t afr[4];
            {
                uint32_t addr = sp + (uint32_t)((16*wm + ((mi & 1) << 3) + l7) * 144
                                                + (16*kk + ((mi >> 1) << 3)) * 2);
                asm volatile(
                    "ldmatrix.sync.aligned.m8n8.x4.shared.b16 {%0,%1,%2,%3},[%4];\n"
                    : "=r"(afr[0]), "=r"(afr[1]), "=r"(afr[2]), "=r"(afr[3])
                    : "r"(addr));
            }
#pragma unroll
            for (int nfp = 0; nfp < 2; nfp++) {
                int n0 = 32*wn + 16*nfp;
                uint32_t b[4];
                uint32_t addr = sb + (uint32_t)((16*kk + ((mi & 1) << 3) + l7) * 272
                                                + (n0 + ((mi >> 1) << 3)) * 2);
                asm volatile(
                    "ldmatrix.sync.aligned.m8n8.x4.trans.shared.b16 {%0,%1,%2,%3},[%4];\n"
                    : "=r"(b[0]), "=r"(b[1]), "=r"(b[2]), "=r"(b[3])
                    : "r"(addr));
                mma_fp16(acc[2*nfp],     afr, b[0], b[1]);
                mma_fp16(acc[2*nfp + 1], afr, b[2], b[3]);
            }
        }
    };

    // ---- prologue: commits [B0][A0][A1][A2][A3] ----
    stage_B(0);
    stage_adj(0); stage_adj(1); stage_adj(2); stage_adj(3);
    asm volatile("cp.async.wait_group 3;\n");   // B0, A0 complete (3 newest pending)
    pgen(0);

    // ---- main loop: commits per iter [A(ch+4)][B(ch+1)] ----
    // wait_group 4: guarantees A(ch+1) (4 newer groups exist in startup,
    //               7 in steady state; 4 is safe in both).
    // wait_group 2: guarantees B(ch) (2 newer: A(ch+4), B(ch+1)).
    for (int ch = 0; ch < NC; ch++) {
        stage_adj(ch + 4);
        stage_B(ch + 1);
        asm volatile("cp.async.wait_group 4;\n");
        if (ch + 1 < NC) pgen(ch + 1);
        asm volatile("cp.async.wait_group 2;\n");
        __syncthreads();                            // B(ch)+P(ch) visible to all
        mma_phase(ch);
    }

    // ---- denominator reduction (8 threads per row) ----
    den += __shfl_xor_sync(0xffffffffu, den, 1);
    den += __shfl_xor_sync(0xffffffffu, den, 2);
    den += __shfl_xor_sync(0xffffffffu, den, 4);
    if (cb == 0) sden[r] = den;
    __syncthreads();

    // ---- epilogue: normalize, write fp32 output ----
    const int g = lane >> 2, t = lane & 3;
    {
        int row0 = 16*wm + g;
        float inv0 = 1.0f / sden[row0];
        float inv1 = 1.0f / sden[row0 + 8];
#pragma unroll
        for (int nf = 0; nf < 4; nf++) {
            int col = 32*wn + 8*nf + 2*t;
            out[(size_t)(i0 + row0)     * FOUT + col    ] = acc[nf][0] * inv0;
            out[(size_t)(i0 + row0)     * FOUT + col + 1] = acc[nf][1] * inv0;
            out[(size_t)(i0 + row0 + 8) * FOUT + col    ] = acc[nf][2] * inv1;
            out[(size_t)(i0 + row0 + 8) * FOUT + col + 1] = acc[nf][3] * inv1;
        }
    }
}

// =====================================================================
extern "C" void kernel_launch(void* const* d_in, const int* in_sizes, int n_in,
                              void* d_out, int out_size)
{
    const float* h   = (const float*)d_in[0];   // [8192,256] f32
    const int*   adj = (const int*)  d_in[1];   // [8192,8192] i32
    const float* Wm  = (const float*)d_in[2];   // [256,128] f32
    const float* a   = (const float*)d_in[3];   // [256,1] f32
    float* out = (float*)d_out;                 // [8192,128] f32

    cudaFuncSetAttribute(gat_main_kernel,
                         cudaFuncAttributeMaxDynamicSharedMemorySize, DYN_SMEM);

    wh_gemm_kernel <<<256, 256>>>(h, Wm, a);
    gat_main_kernel<<<GRID_MAIN, 256, DYN_SMEM>>>(adj, out);
}